// round 6
// baseline (speedup 1.0000x reference)
#include <cuda_runtime.h>
#include <cuda_bf16.h>
#include <cstdint>

typedef unsigned int u32;

#define D        512
#define BDIM     1024
#define C        200
#define NKEYS    50000
#define BM       64
#define BN       128
#define NTILES   391
#define NPAD     (NTILES * BN)
#define BTILES   (BDIM / BM)          // 16
#define NGROUPS  9                    // 144 CTAs = one wave
#define NSTAGES  4
#define KCH      128                  // int8 k per chunk
#define SB8      144                  // B stage row stride (int8 bytes)
#define SA8      528                  // A panel row stride (int8 bytes)
#define CP       201

#define BS_BYTES (BN * SB8)                    // 18432
#define OFF_BS   0
#define OFF_AS   (NSTAGES * BS_BYTES)          // 73728
#define OFF_CSH  (OFF_AS + BM * SA8)           // 107520
#define OFF_LABS (OFF_CSH + BM * CP * 4)       // 158976
#define OFF_FK   (OFF_LABS + BN * 4)           // 159488
#define OFF_FQ   (OFF_FK + BN * 4)             // 160000
#define SMEM_DYN (OFF_FQ + BM * 4)             // 160256

// ---------------- device scratch ----------------
__device__ __align__(16) signed char g_q8[BDIM][D];
__device__ float g_qs[BDIM];
__device__ float g_qf[BDIM * D];
__device__ float g_tf[C * D];
__device__ __align__(16) signed char g_k8[NPAD][D];   // tail rows stay zero
__device__ float g_ks[NPAD];
__device__ int   g_lab[NPAD];
__device__ float g_part[NGROUPS * BDIM * C];

// ---------------- helpers ----------------
__device__ __forceinline__ u32 smem_u32(const void* p) {
    u32 a;
    asm("{ .reg .u64 t; cvta.to.shared.u64 t, %1; cvt.u32.u64 %0, t; }" : "=r"(a) : "l"(p));
    return a;
}

__device__ __forceinline__ void ldmx4(u32& r0, u32& r1, u32& r2, u32& r3, const void* p) {
    u32 addr = smem_u32(p);
    asm volatile("ldmatrix.sync.aligned.m8n8.x4.shared.b16 {%0,%1,%2,%3}, [%4];\n"
                 : "=r"(r0), "=r"(r1), "=r"(r2), "=r"(r3) : "r"(addr));
}

__device__ __forceinline__ void mma_s8(int* d, const u32* a, const u32* b) {
    asm volatile(
        "mma.sync.aligned.m16n8k32.row.col.s32.s8.s8.s32 "
        "{%0,%1,%2,%3}, {%4,%5,%6,%7}, {%8,%9}, {%0,%1,%2,%3};\n"
        : "+r"(d[0]), "+r"(d[1]), "+r"(d[2]), "+r"(d[3])
        : "r"(a[0]), "r"(a[1]), "r"(a[2]), "r"(a[3]), "r"(b[0]), "r"(b[1]));
}

__device__ __forceinline__ void cp16(u32 dst, const void* src) {
    asm volatile("cp.async.cg.shared.global [%0], [%1], 16;" :: "r"(dst), "l"(src));
}
#define CP_COMMIT() asm volatile("cp.async.commit_group;" ::: "memory")
#define CP_WAIT3()  asm volatile("cp.async.wait_group 3;" ::: "memory")

// ---------------- prep: normalize + int8 quantize (per-row scale) ----------------
__device__ __forceinline__ float blk_sumsq(float4 x) {
    int t = threadIdx.x;
    float ss = x.x * x.x + x.y * x.y + x.z * x.z + x.w * x.w;
#pragma unroll
    for (int o = 16; o; o >>= 1) ss += __shfl_xor_sync(0xffffffffu, ss, o);
    __shared__ float ws[4];
    if ((t & 31) == 0) ws[t >> 5] = ss;
    __syncthreads();
    return ws[0] + ws[1] + ws[2] + ws[3];
}

__device__ __forceinline__ float blk_max(float m) {
    int t = threadIdx.x;
#pragma unroll
    for (int o = 16; o; o >>= 1) m = fmaxf(m, __shfl_xor_sync(0xffffffffu, m, o));
    __shared__ float wm[4];
    if ((t & 31) == 0) wm[t >> 5] = m;
    __syncthreads();
    return fmaxf(fmaxf(wm[0], wm[1]), fmaxf(wm[2], wm[3]));
}

__device__ __forceinline__ u32 pack4(float4 y, float sc) {
    int a = __float2int_rn(y.x * sc), b = __float2int_rn(y.y * sc);
    int c = __float2int_rn(y.z * sc), d = __float2int_rn(y.w * sc);
    return (u32)(a & 255) | ((u32)(b & 255) << 8) | ((u32)(c & 255) << 16) | ((u32)(d & 255) << 24);
}

__global__ void prep_q(const float* __restrict__ img) {
    int row = blockIdx.x, t = threadIdx.x;
    float4 x = ((const float4*)(img + row * D))[t];
    float inv = rsqrtf(blk_sumsq(x));
    float4 y = make_float4(x.x * inv, x.y * inv, x.z * inv, x.w * inv);
    ((float4*)(g_qf + row * D))[t] = y;
    float m = fmaxf(fmaxf(fabsf(y.x), fabsf(y.y)), fmaxf(fabsf(y.z), fabsf(y.w)));
    float M = blk_max(m);
    ((u32*)g_q8[row])[t] = pack4(y, 127.f / M);
    if (t == 0) g_qs[row] = M * (1.f / 127.f);
}

__global__ void prep_t(const float* __restrict__ txt) {
    int row = blockIdx.x, t = threadIdx.x;
    float4 x = ((const float4*)(txt + row * D))[t];
    float inv = rsqrtf(blk_sumsq(x));
    ((float4*)(g_tf + row * D))[t] = make_float4(x.x * inv, x.y * inv, x.z * inv, x.w * inv);
}

__global__ void prep_k(const float* __restrict__ keys, const int* __restrict__ labels) {
    int row = blockIdx.x, t = threadIdx.x;
    float4 x = ((const float4*)(keys + row * D))[t];
    float inv = rsqrtf(blk_sumsq(x));
    float4 y = make_float4(x.x * inv, x.y * inv, x.z * inv, x.w * inv);
    float m = fmaxf(fmaxf(fabsf(y.x), fabsf(y.y)), fmaxf(fabsf(y.z), fabsf(y.w)));
    float M = blk_max(m);
    ((u32*)g_k8[row])[t] = pack4(y, 127.f / M);
    if (t == 0) {
        g_ks[row] = M * (1.f / 127.f);
        int l = labels[row];
        g_lab[row] = (l < 0) ? 0 : ((l >= C) ? C - 1 : l);
    }
}

// ---------------- main: pipelined IMMA GEMM + exp-scatter ----------------
extern __shared__ unsigned char smraw[];

__global__ void __launch_bounds__(256, 1) gemm_scatter() {
    signed char* As = (signed char*)(smraw + OFF_AS);
    float* csh  = (float*)(smraw + OFF_CSH);
    int*   labs = (int*)(smraw + OFF_LABS);
    float* fksh = (float*)(smraw + OFF_FK);
    float* fqsh = (float*)(smraw + OFF_FQ);

    int tid = threadIdx.x;
    int lane = tid & 31, wid = tid >> 5;
    int wm = wid >> 2, wn = wid & 3;      // 2 x 4 warps, warp tile 32x32
    int bt = blockIdx.x;
    int ng = blockIdx.y;

    for (int i = tid; i < BM * CP; i += 256) csh[i] = 0.f;
    if (tid < BM) fqsh[tid] = g_qs[bt * BM + tid];

    // group 0: A panel 64 x 512 int8
    {
        u32 asb = smem_u32(As);
        const char* src = (const char*)&g_q8[bt * BM][0];
#pragma unroll
        for (int k = 0; k < 8; k++) {
            int idx = tid + k * 256;          // 0..2047
            int r = idx >> 5, c = idx & 31;
            cp16(asb + (u32)(r * SA8 + c * 16), src + r * D + c * 16);
        }
        CP_COMMIT();
    }

    int nt = (NTILES - 1 - ng) / NGROUPS + 1;
    int nchunks = nt * 4;                     // 4 chunks of k=128 per tile
    u32 bsb = smem_u32(smraw + OFF_BS);

    // prologue: chunks 0..2
    for (int p = 0; p < 3; p++) {
        int tloc = p >> 2, ch = p & 3;
        int n0 = (ng + tloc * NGROUPS) * BN;
        u32 sb = bsb + (u32)(p % NSTAGES) * BS_BYTES;
        const char* src = (const char*)&g_k8[n0][0] + ch * KCH;
#pragma unroll
        for (int k = 0; k < 4; k++) {
            int idx = tid + k * 256;          // 0..1023
            int r = idx >> 3, s = idx & 7;
            cp16(sb + (u32)(r * SB8 + s * 16), src + r * D + s * 16);
        }
        CP_COMMIT();
    }

    int acc[2][4][4];
#pragma unroll
    for (int mi = 0; mi < 2; mi++)
#pragma unroll
        for (int ni = 0; ni < 4; ni++)
#pragma unroll
            for (int e = 0; e < 4; e++) acc[mi][ni][e] = 0;

    for (int g = 0; g < nchunks; g++) {
        __syncthreads();
        int pf = g + 3;
        if (pf < nchunks) {
            int tloc = pf >> 2, ch = pf & 3;
            int n0 = (ng + tloc * NGROUPS) * BN;
            u32 sb = bsb + (u32)(pf % NSTAGES) * BS_BYTES;
            const char* src = (const char*)&g_k8[n0][0] + ch * KCH;
#pragma unroll
            for (int k = 0; k < 4; k++) {
                int idx = tid + k * 256;
                int r = idx >> 3, s = idx & 7;
                cp16(sb + (u32)(r * SB8 + s * 16), src + r * D + s * 16);
            }
        }
        CP_COMMIT();
        CP_WAIT3();
        __syncthreads();

        int ch = g & 3;
        if (ch == 0 && tid < BN) {
            int n0 = (ng + (g >> 2) * NGROUPS) * BN;
            labs[tid] = g_lab[n0 + tid];
            fksh[tid] = g_ks[n0 + tid];
        }

        signed char* Bst = (signed char*)(smraw + OFF_BS + (g % NSTAGES) * BS_BYTES);
#pragma unroll
        for (int ks = 0; ks < 4; ks++) {      // 4 x k32
            u32 afr[2][4];
#pragma unroll
            for (int mi = 0; mi < 2; mi++) {
                int rA = wm * 32 + mi * 16 + (lane & 7) + ((lane >> 3) & 1) * 8;
                int kA = ch * KCH + ks * 32 + ((lane >> 4) & 1) * 16;
                ldmx4(afr[mi][0], afr[mi][1], afr[mi][2], afr[mi][3], As + rA * SA8 + kA);
            }
            u32 bfr[4][2];
#pragma unroll
            for (int gg = 0; gg < 2; gg++) {
                int rB = wn * 32 + gg * 16 + (lane & 7) + ((lane >> 4) & 1) * 8;
                int kB = ks * 32 + ((lane >> 3) & 1) * 16;
                u32 r0, r1, r2, r3;
                ldmx4(r0, r1, r2, r3, Bst + rB * SB8 + kB);
                bfr[gg * 2 + 0][0] = r0; bfr[gg * 2 + 0][1] = r1;
                bfr[gg * 2 + 1][0] = r2; bfr[gg * 2 + 1][1] = r3;
            }
#pragma unroll
            for (int mi = 0; mi < 2; mi++)
#pragma unroll
                for (int ni = 0; ni < 4; ni++)
                    mma_s8(acc[mi][ni], afr[mi], bfr[ni]);
        }

        if (ch == 3) {                        // tile done: dequant + exp + scatter
            int n0 = (ng + (g >> 2) * NGROUPS) * BN;
#pragma unroll
            for (int mi = 0; mi < 2; mi++) {
                int rb = wm * 32 + mi * 16 + (lane >> 2);
                float fq0 = 5.f * fqsh[rb], fq1 = 5.f * fqsh[rb + 8];
#pragma unroll
                for (int ni = 0; ni < 4; ni++) {
                    int cb = wn * 32 + ni * 8 + 2 * (lane & 3);
#pragma unroll
                    for (int e = 0; e < 4; e++) {
                        int r = rb + ((e >= 2) ? 8 : 0);
                        int c = cb + (e & 1);
                        if (n0 + c < NKEYS) {
                            float fq = (e >= 2) ? fq1 : fq0;
                            float v = __expf((float)acc[mi][ni][e] * fq * fksh[c]);
                            atomicAdd(&csh[r * CP + labs[c]], v);
                        }
                        acc[mi][ni][e] = 0;
                    }
                }
            }
        }
    }

    __syncthreads();
    float* dst = g_part + ((size_t)ng * BDIM + bt * BM) * C;
    for (int i = tid; i < BM * C; i += 256) {
        int r = i / C, c = i % C;
        dst[i] = csh[r * CP + c];
    }
}

// ---------------- z branch + combine partials ----------------
__global__ void __launch_bounds__(256) zcombine(float* __restrict__ out) {
    __shared__ float a2[64][17];
    __shared__ float b2[64][17];
    int tid = threadIdx.x;
    int tx = tid & 15, ty = tid >> 4;
    int rb = blockIdx.x * 64, cb = blockIdx.y * 64;

    float acc[4][4];
#pragma unroll
    for (int i = 0; i < 4; i++)
#pragma unroll
        for (int j = 0; j < 4; j++) acc[i][j] = 0.f;

    for (int k0 = 0; k0 < D; k0 += 16) {
        __syncthreads();
#pragma unroll
        for (int j = 0; j < 4; j++) {
            int idx = tid + j * 256;
            int r = idx >> 4, c = idx & 15;
            a2[r][c] = g_qf[(rb + r) * D + k0 + c];
            int cls = cb + r;
            b2[r][c] = (cls < C) ? g_tf[cls * D + k0 + c] : 0.f;
        }
        __syncthreads();
#pragma unroll
        for (int k = 0; k < 16; k++) {
            float av[4], bv[4];
#pragma unroll
            for (int i = 0; i < 4; i++) { av[i] = a2[ty * 4 + i][k]; bv[i] = b2[tx * 4 + i][k]; }
#pragma unroll
            for (int i = 0; i < 4; i++)
#pragma unroll
                for (int j = 0; j < 4; j++) acc[i][j] += av[i] * bv[j];
        }
    }

#pragma unroll
    for (int i = 0; i < 4; i++)
#pragma unroll
        for (int j = 0; j < 4; j++) {
            int r = rb + ty * 4 + i, c = cb + tx * 4 + j;
            if (c < C) {
                float s = 0.f;
#pragma unroll
                for (int gg = 0; gg < NGROUPS; gg++)
                    s += g_part[((size_t)gg * BDIM + r) * C + c];
                out[r * C + c] = 50.f * acc[i][j] + 0.5f * s;
            }
        }
}

// ---------------- launch ----------------
extern "C" void kernel_launch(void* const* d_in, const int* in_sizes, int n_in,
                              void* d_out, int out_size) {
    const float* img  = (const float*)d_in[0];
    const float* txt  = (const float*)d_in[1];
    const float* keys = (const float*)d_in[2];
    const int*   labs = (const int*)d_in[3];
    float* out = (float*)d_out;

    cudaFuncSetAttribute(gemm_scatter, cudaFuncAttributeMaxDynamicSharedMemorySize,
                         SMEM_DYN);

    prep_q<<<BDIM, 128>>>(img);
    prep_t<<<C, 128>>>(txt);
    prep_k<<<NKEYS, 128>>>(keys, labs);
    gemm_scatter<<<dim3(BTILES, NGROUPS), 256, SMEM_DYN>>>();
    zcombine<<<dim3(BDIM / 64, 4), 256>>>(out);
}

// round 7
// speedup vs baseline: 1.5253x; 1.5253x over previous
#include <cuda_runtime.h>
#include <cuda_bf16.h>
#include <cstdint>

typedef unsigned int u32;

#define D        512
#define BDIM     1024
#define C        200
#define NKEYS    50000
#define BM       64
#define BN       128
#define NTILES   391
#define NPAD     (NTILES * BN)
#define BTILES   (BDIM / BM)          // 16
#define NGROUPS  9                    // 144 CTAs = one wave
#define NSTAGES  4
#define NTHREADS 512
#define SB       72                   // B stage row stride (bf16)
#define SAQ      520                  // A panel row stride (bf16)
#define CP       201

#define BS_BYTES (BN * SB * 2)                 // 18432
#define OFF_BS   0
#define OFF_AS   (NSTAGES * BS_BYTES)          // 73728
#define OFF_CSH  (OFF_AS + BM * SAQ * 2)       // 140288
#define OFF_LABS (OFF_CSH + BM * CP * 4)       // 191744
#define SMEM_DYN (OFF_LABS + BN * 4)           // 192256

// ---------------- device scratch ----------------
__device__ __align__(16) __nv_bfloat16 g_qbf[BDIM][D];
__device__ float g_qf[BDIM * D];
__device__ float g_tf[C * D];
__device__ __align__(16) __nv_bfloat16 g_kbf[NPAD][D];   // tail rows stay zero
__device__ int   g_lab[NPAD];
__device__ float g_part[NGROUPS * BDIM * C];

// ---------------- helpers ----------------
__device__ __forceinline__ u32 smem_u32(const void* p) {
    u32 a;
    asm("{ .reg .u64 t; cvta.to.shared.u64 t, %1; cvt.u32.u64 %0, t; }" : "=r"(a) : "l"(p));
    return a;
}

__device__ __forceinline__ void ldmx4(u32& r0, u32& r1, u32& r2, u32& r3, const void* p) {
    u32 addr = smem_u32(p);
    asm volatile("ldmatrix.sync.aligned.m8n8.x4.shared.b16 {%0,%1,%2,%3}, [%4];\n"
                 : "=r"(r0), "=r"(r1), "=r"(r2), "=r"(r3) : "r"(addr));
}

__device__ __forceinline__ void mma_bf16(float* d, const u32* a, const u32* b) {
    asm volatile(
        "mma.sync.aligned.m16n8k16.row.col.f32.bf16.bf16.f32 "
        "{%0,%1,%2,%3}, {%4,%5,%6,%7}, {%8,%9}, {%0,%1,%2,%3};\n"
        : "+f"(d[0]), "+f"(d[1]), "+f"(d[2]), "+f"(d[3])
        : "r"(a[0]), "r"(a[1]), "r"(a[2]), "r"(a[3]), "r"(b[0]), "r"(b[1]));
}

__device__ __forceinline__ void cp16(u32 dst, const void* src) {
    asm volatile("cp.async.cg.shared.global [%0], [%1], 16;" :: "r"(dst), "l"(src));
}
#define CP_COMMIT() asm volatile("cp.async.commit_group;" ::: "memory")
#define CP_WAIT3()  asm volatile("cp.async.wait_group 3;" ::: "memory")

// ---------------- prep ----------------
__device__ __forceinline__ float blk_sumsq(float4 x) {
    int t = threadIdx.x;
    float ss = x.x * x.x + x.y * x.y + x.z * x.z + x.w * x.w;
#pragma unroll
    for (int o = 16; o; o >>= 1) ss += __shfl_xor_sync(0xffffffffu, ss, o);
    __shared__ float ws[4];
    if ((t & 31) == 0) ws[t >> 5] = ss;
    __syncthreads();
    return ws[0] + ws[1] + ws[2] + ws[3];
}

__global__ void prep_q(const float* __restrict__ img) {
    int row = blockIdx.x, t = threadIdx.x;
    float4 x = ((const float4*)(img + row * D))[t];
    float inv = rsqrtf(blk_sumsq(x));
    float4 y = make_float4(x.x * inv, x.y * inv, x.z * inv, x.w * inv);
    ((float4*)(g_qf + row * D))[t] = y;
    __nv_bfloat162* dst = (__nv_bfloat162*)&g_qbf[row][0];
    dst[2 * t + 0] = __floats2bfloat162_rn(y.x, y.y);
    dst[2 * t + 1] = __floats2bfloat162_rn(y.z, y.w);
}

__global__ void prep_t(const float* __restrict__ txt) {
    int row = blockIdx.x, t = threadIdx.x;
    float4 x = ((const float4*)(txt + row * D))[t];
    float inv = rsqrtf(blk_sumsq(x));
    ((float4*)(g_tf + row * D))[t] = make_float4(x.x * inv, x.y * inv, x.z * inv, x.w * inv);
}

__global__ void prep_k(const float* __restrict__ keys, const int* __restrict__ labels) {
    int row = blockIdx.x, t = threadIdx.x;
    float4 x = ((const float4*)(keys + row * D))[t];
    float inv = rsqrtf(blk_sumsq(x));
    __nv_bfloat162* dst = (__nv_bfloat162*)&g_kbf[row][0];
    dst[2 * t + 0] = __floats2bfloat162_rn(x.x * inv, x.y * inv);
    dst[2 * t + 1] = __floats2bfloat162_rn(x.z * inv, x.w * inv);
    if (t == 0) {
        int l = labels[row];
        g_lab[row] = (l < 0) ? 0 : ((l >= C) ? C - 1 : l);
    }
}

// ---------------- main: pipelined HMMA GEMM + exp-scatter, 16 warps ----------------
extern __shared__ unsigned char smraw[];

__global__ void __launch_bounds__(NTHREADS, 1) gemm_scatter() {
    __nv_bfloat16* As = (__nv_bfloat16*)(smraw + OFF_AS);
    float* csh  = (float*)(smraw + OFF_CSH);
    int*   labs = (int*)(smraw + OFF_LABS);

    int tid = threadIdx.x;
    int lane = tid & 31, wid = tid >> 5;
    int wm = wid >> 2, wn = wid & 3;      // 4 x 4 warps, warp tile 16x32
    int bt = blockIdx.x;
    int ng = blockIdx.y;

    for (int i = tid; i < BM * CP; i += NTHREADS) csh[i] = 0.f;

    // group 0: A panel 64 x 512 bf16
    {
        u32 asb = smem_u32(As);
        const char* src = (const char*)&g_qbf[bt * BM][0];
#pragma unroll
        for (int k = 0; k < 8; k++) {
            int idx = tid + k * NTHREADS;     // 0..4095
            int r = idx >> 6, c = idx & 63;
            cp16(asb + (u32)(r * (SAQ * 2) + c * 16), src + r * (D * 2) + c * 16);
        }
        CP_COMMIT();
    }

    int nt = (NTILES - 1 - ng) / NGROUPS + 1;   // strided tiles: ng, ng+9, ...
    int nchunks = nt * 8;
    u32 bsb = smem_u32(smraw + OFF_BS);

    // prologue: chunks 0..2
    for (int p = 0; p < 3; p++) {
        int tloc = p >> 3, ch = p & 7;
        int n0 = (ng + tloc * NGROUPS) * BN;
        u32 sb = bsb + (u32)(p % NSTAGES) * BS_BYTES;
        const char* src = (const char*)&g_kbf[n0][0] + ch * 128;
#pragma unroll
        for (int k = 0; k < 2; k++) {
            int idx = tid + k * NTHREADS;     // 0..1023
            int r = idx >> 3, s = idx & 7;
            cp16(sb + (u32)(r * (SB * 2) + s * 16), src + r * (D * 2) + s * 16);
        }
        CP_COMMIT();
    }

    float acc[4][4];
#pragma unroll
    for (int ni = 0; ni < 4; ni++)
#pragma unroll
        for (int e = 0; e < 4; e++) acc[ni][e] = 0.f;

    for (int g = 0; g < nchunks; g++) {
        __syncthreads();                      // stage (g+3)%4 free to overwrite
        int pf = g + 3;
        if (pf < nchunks) {
            int tloc = pf >> 3, ch = pf & 7;
            int n0 = (ng + tloc * NGROUPS) * BN;
            u32 sb = bsb + (u32)(pf % NSTAGES) * BS_BYTES;
            const char* src = (const char*)&g_kbf[n0][0] + ch * 128;
#pragma unroll
            for (int k = 0; k < 2; k++) {
                int idx = tid + k * NTHREADS;
                int r = idx >> 3, s = idx & 7;
                cp16(sb + (u32)(r * (SB * 2) + s * 16), src + r * (D * 2) + s * 16);
            }
        }
        CP_COMMIT();
        CP_WAIT3();                           // chunk g (and A panel) resident
        __syncthreads();

        int ch = g & 7;
        if (ch == 0 && tid < BN) {
            int n0 = (ng + (g >> 3) * NGROUPS) * BN;
            labs[tid] = g_lab[n0 + tid];
        }

        __nv_bfloat16* Bst = (__nv_bfloat16*)(smraw + OFF_BS + (g % NSTAGES) * BS_BYTES);
#pragma unroll
        for (int ks = 0; ks < 4; ks++) {
            int kk = ks * 16;
            u32 afr[4];
            {
                int rA = wm * 16 + (lane & 7) + ((lane >> 3) & 1) * 8;
                int kA = ch * 64 + kk + ((lane >> 4) & 1) * 8;
                ldmx4(afr[0], afr[1], afr[2], afr[3], As + rA * SAQ + kA);
            }
            u32 bfr[4][2];
#pragma unroll
            for (int gg = 0; gg < 2; gg++) {
                int rB = wn * 32 + gg * 16 + (lane & 7) + ((lane >> 4) & 1) * 8;
                int kB = kk + ((lane >> 3) & 1) * 8;
                u32 r0, r1, r2, r3;
                ldmx4(r0, r1, r2, r3, Bst + rB * SB + kB);
                bfr[gg * 2 + 0][0] = r0; bfr[gg * 2 + 0][1] = r1;
                bfr[gg * 2 + 1][0] = r2; bfr[gg * 2 + 1][1] = r3;
            }
#pragma unroll
            for (int ni = 0; ni < 4; ni++)
                mma_bf16(acc[ni], afr, bfr[ni]);
        }

        if (ch == 7) {                        // tile done: exp + scatter
            int n0 = (ng + (g >> 3) * NGROUPS) * BN;
            int rb = wm * 16 + (lane >> 2);
#pragma unroll
            for (int ni = 0; ni < 4; ni++) {
                int cb = wn * 32 + ni * 8 + 2 * (lane & 3);
#pragma unroll
                for (int e = 0; e < 4; e++) {
                    int r = rb + ((e >= 2) ? 8 : 0);
                    int c = cb + (e & 1);
                    if (n0 + c < NKEYS) {
                        float v = __expf(5.0f * acc[ni][e]);
                        atomicAdd(&csh[r * CP + labs[c]], v);
                    }
                    acc[ni][e] = 0.f;
                }
            }
        }
    }

    __syncthreads();
    float* dst = g_part + ((size_t)ng * BDIM + bt * BM) * C;
    for (int i = tid; i < BM * C; i += NTHREADS) {
        int r = i / C, c = i % C;
        dst[i] = csh[r * CP + c];
    }
}

// ---------------- z branch + combine partials ----------------
__global__ void __launch_bounds__(256) zcombine(float* __restrict__ out) {
    __shared__ float a2[64][17];
    __shared__ float b2[64][17];
    int tid = threadIdx.x;
    int tx = tid & 15, ty = tid >> 4;
    int rb = blockIdx.x * 64, cb = blockIdx.y * 64;

    float acc[4][4];
#pragma unroll
    for (int i = 0; i < 4; i++)
#pragma unroll
        for (int j = 0; j < 4; j++) acc[i][j] = 0.f;

    for (int k0 = 0; k0 < D; k0 += 16) {
        __syncthreads();
#pragma unroll
        for (int j = 0; j < 4; j++) {
            int idx = tid + j * 256;
            int r = idx >> 4, c = idx & 15;
            a2[r][c] = g_qf[(rb + r) * D + k0 + c];
            int cls = cb + r;
            b2[r][c] = (cls < C) ? g_tf[cls * D + k0 + c] : 0.f;
        }
        __syncthreads();
#pragma unroll
        for (int k = 0; k < 16; k++) {
            float av[4], bv[4];
#pragma unroll
            for (int i = 0; i < 4; i++) { av[i] = a2[ty * 4 + i][k]; bv[i] = b2[tx * 4 + i][k]; }
#pragma unroll
            for (int i = 0; i < 4; i++)
#pragma unroll
                for (int j = 0; j < 4; j++) acc[i][j] += av[i] * bv[j];
        }
    }

#pragma unroll
    for (int i = 0; i < 4; i++)
#pragma unroll
        for (int j = 0; j < 4; j++) {
            int r = rb + ty * 4 + i, c = cb + tx * 4 + j;
            if (c < C) {
                float s = 0.f;
#pragma unroll
                for (int gg = 0; gg < NGROUPS; gg++)
                    s += g_part[((size_t)gg * BDIM + r) * C + c];
                out[r * C + c] = 50.f * acc[i][j] + 0.5f * s;
            }
        }
}

// ---------------- launch ----------------
extern "C" void kernel_launch(void* const* d_in, const int* in_sizes, int n_in,
                              void* d_out, int out_size) {
    const float* img  = (const float*)d_in[0];
    const float* txt  = (const float*)d_in[1];
    const float* keys = (const float*)d_in[2];
    const int*   labs = (const int*)d_in[3];
    float* out = (float*)d_out;

    cudaFuncSetAttribute(gemm_scatter, cudaFuncAttributeMaxDynamicSharedMemorySize,
                         SMEM_DYN);

    prep_q<<<BDIM, 128>>>(img);
    prep_t<<<C, 128>>>(txt);
    prep_k<<<NKEYS, 128>>>(keys, labs);
    gemm_scatter<<<dim3(BTILES, NGROUPS), NTHREADS, SMEM_DYN>>>();
    zcombine<<<dim3(BDIM / 64, 4), 256>>>(out);
}